// round 1
// baseline (speedup 1.0000x reference)
#include <cuda_runtime.h>
#include <cstdint>

#define BQ   256
#define NQ   65536
#define HIDQ 64
#define TPB  256
#define TILE 1024
#define SUB  (TILE / TPB)   // 4
#define RROWS 8

__device__ __forceinline__ float tanhax(float x) {
    float y;
    asm("tanh.approx.f32 %0, %1;" : "=f"(y) : "f"(x));
    return y;
}

__global__ __launch_bounds__(TPB) void soen_kernel(
    const float* __restrict__ phi, const float* __restrict__ s,
    const float* __restrict__ i_b, const float* __restrict__ w1,
    const float* __restrict__ b1,  const float* __restrict__ w2,
    const float* __restrict__ b2,  const int* __restrict__ fidx,
    float* __restrict__ out)
{
    __shared__ float4 q4[HIDQ];        // (w1[0][k], w1[1][k], w1[2][k], b1[k])
    __shared__ float  vv[HIDQ];        // w2[k]
    __shared__ int    cnt3;
    __shared__ int    col3[TILE];      // local column index of func3 entries
    __shared__ float  ib3[TILE];
    __shared__ float2 ps3[TILE];       // (p, s) stash for func3, single-buffered
    __shared__ float  out_s[2][TILE];  // output staging, double-buffered

    const int t        = threadIdx.x;
    const int lane     = t & 31;
    const int tileBase = blockIdx.x * TILE;
    const int r0       = blockIdx.y * RROWS;

    if (t < HIDQ) {
        q4[t] = make_float4(w1[t], w1[HIDQ + t], w1[2 * HIDQ + t], b1[t]);
        vv[t] = w2[t];
    }
    if (t == 0) cnt3 = 0;
    __syncthreads();

    // ---- setup: compact func3 columns of this tile (warp ballot + 1 shared atomic/warp) ----
    int myf[SUB];
    int myrank[SUB];
#pragma unroll
    for (int i = 0; i < SUB; i++) {
        const int lc  = i * TPB + t;
        const int col = tileBase + lc;
        const int f   = fidx[col];
        myf[i] = f;
        unsigned mask = __ballot_sync(0xffffffffu, f == 3);
        int rank = -1;
        if (mask) {
            const int leader = __ffs(mask) - 1;
            int base = 0;
            if (lane == leader) base = atomicAdd(&cnt3, __popc(mask));
            base = __shfl_sync(0xffffffffu, base, leader);
            if (f == 3) {
                rank = base + __popc(mask & ((1u << lane) - 1u));
                col3[rank] = lc;
                ib3[rank]  = i_b[col];
            }
        }
        myrank[i] = rank;
    }
    __syncthreads();
    const int   c3    = cnt3;
    const float bias2 = b2[0];

    for (int rr = 0; rr < RROWS; rr++) {
        const int    r      = r0 + rr;
        const int    buf    = rr & 1;
        const size_t rowOff = (size_t)r * NQ + tileBase;

        // ---- Phase A: coalesced loads, cheap funcs branchless, stash func3 (p,s) ----
#pragma unroll
        for (int i = 0; i < SUB; i++) {
            const int   lc = i * TPB + t;
            const float ph = phi[rowOff + lc];
            const float sv = s[rowOff + lc];
            const float p  = ph - rintf(ph);
            if (myf[i] == 3) {
                ps3[myrank[i]] = make_float2(p, sv);
            } else {
                const float g0 = fmaxf(fabsf(p) - sv, 0.0f);
                const float g1 = tanhax(p) * (1.0f - sv);
                const float g2 = exp2f(p * p * (-14.4269504088896340736f)) - sv;
                out_s[buf][lc] = (myf[i] == 0) ? g0 : ((myf[i] == 1) ? g1 : g2);
            }
        }
        __syncthreads();

        // ---- Phase B: warp-uniform MLP over compacted func3 list ----
        for (int j = t; j < c3; j += TPB) {
            const float2 ps  = ps3[j];
            const float  ibv = ib3[j];
            float acc = bias2;
#pragma unroll 16
            for (int k = 0; k < HIDQ; k++) {
                const float4 w = q4[k];
                const float  z = fmaf(ps.x, w.x, fmaf(ps.y, w.y, fmaf(ibv, w.z, w.w)));
                acc = fmaf(tanhax(z), vv[k], acc);
            }
            out_s[buf][col3[j]] = acc;
        }
        __syncthreads();

        // ---- Phase C: coalesced stores ----
#pragma unroll
        for (int i = 0; i < SUB; i++) {
            const int lc = i * TPB + t;
            out[rowOff + lc] = out_s[buf][lc];
        }
    }
}

extern "C" void kernel_launch(void* const* d_in, const int* in_sizes, int n_in,
                              void* d_out, int out_size)
{
    const float* phi  = (const float*)d_in[0];
    const float* s    = (const float*)d_in[1];
    const float* i_b  = (const float*)d_in[2];
    const float* w1   = (const float*)d_in[3];
    const float* b1   = (const float*)d_in[4];
    const float* w2   = (const float*)d_in[5];
    const float* b2   = (const float*)d_in[6];
    const int*   fidx = (const int*)d_in[7];
    float*       out  = (float*)d_out;

    dim3 grid(NQ / TILE, BQ / RROWS);   // (64, 32) = 2048 blocks
    soen_kernel<<<grid, TPB>>>(phi, s, i_b, w1, b1, w2, b2, fidx, out);
}

// round 2
// speedup vs baseline: 1.1414x; 1.1414x over previous
#include <cuda_runtime.h>
#include <cstdint>

#define NQ    65536
#define HIDQ  64
#define TPB   256
#define TILE  1024
#define RROWS 8

__device__ __forceinline__ float tanhax(float x) {
    float y; asm("tanh.approx.f32 %0, %1;" : "=f"(y) : "f"(x)); return y;
}

__global__ __launch_bounds__(TPB) void soen_kernel(
    const float* __restrict__ phi, const float* __restrict__ s,
    const float* __restrict__ i_b, const float* __restrict__ w1,
    const float* __restrict__ b1,  const float* __restrict__ w2,
    const float* __restrict__ b2,  const int* __restrict__ fidx,
    float* __restrict__ out)
{
    __shared__ float4 q4[HIDQ];   // (w1[0][k], w1[1][k], w1[2][k], b1[k])
    __shared__ float  vv[HIDQ];   // w2[k]
    __shared__ int    cnt3;
    __shared__ int    col3[TILE]; // local column idx of func3 columns
    __shared__ float  ib3[TILE];  // i_b for those columns

    const int t        = threadIdx.x;
    const int lane     = t & 31;
    const int tileBase = blockIdx.x * TILE;
    const int r0       = blockIdx.y * RROWS;

    if (t < HIDQ) {
        q4[t] = make_float4(w1[t], w1[HIDQ + t], w1[2 * HIDQ + t], b1[t]);
        vv[t] = w2[t];
    }
    if (t == 0) cnt3 = 0;
    __syncthreads();

    // ---- setup: compact func3 columns (thread t owns cols 4t..4t+3) ----
    const int4 fi4 = ((const int4*)(fidx + tileBase))[t];
    int f[4] = {fi4.x, fi4.y, fi4.z, fi4.w};
#pragma unroll
    for (int e = 0; e < 4; e++) {
        const unsigned mask = __ballot_sync(0xffffffffu, f[e] == 3);
        if (mask) {
            const int leader = __ffs(mask) - 1;
            int base = 0;
            if (lane == leader) base = atomicAdd(&cnt3, __popc(mask));
            base = __shfl_sync(0xffffffffu, base, leader);
            if (f[e] == 3) {
                const int rank = base + __popc(mask & ((1u << lane) - 1u));
                const int lc   = 4 * t + e;
                col3[rank] = lc;
                ib3[rank]  = i_b[tileBase + lc];
            }
        }
    }
    __syncthreads();
    const int   c3    = cnt3;
    const float bias2 = b2[0];

    // ---- Phase A: float4 coalesced, cheap funcs, predicated direct stores ----
#pragma unroll
    for (int rr = 0; rr < RROWS; rr++) {
        const size_t rowOff = (size_t)(r0 + rr) * NQ + tileBase;
        const float4 ph4 = ((const float4*)(phi + rowOff))[t];
        const float4 sv4 = ((const float4*)(s   + rowOff))[t];
        const float phv[4] = {ph4.x, ph4.y, ph4.z, ph4.w};
        const float svv[4] = {sv4.x, sv4.y, sv4.z, sv4.w};
#pragma unroll
        for (int e = 0; e < 4; e++) {
            const float p  = phv[e] - rintf(phv[e]);
            const float sv = svv[e];
            const float g0 = fmaxf(fabsf(p) - sv, 0.0f);
            const float g1 = tanhax(p) * (1.0f - sv);
            const float g2 = exp2f(p * p * (-14.4269504088896340736f)) - sv;
            const float res = (f[e] == 0) ? g0 : ((f[e] == 1) ? g1 : g2);
            if (f[e] != 3) out[rowOff + 4 * t + e] = res;
        }
    }

    // ---- Phase B: one func3 COLUMN x 8 rows per thread ----
    for (int j = t; j < c3; j += TPB) {
        const int    lc   = col3[j];
        const float  ibv  = ib3[j];
        const size_t base = (size_t)r0 * NQ + tileBase + lc;

        float p[RROWS], sv[RROWS], acc[RROWS];
#pragma unroll
        for (int rr = 0; rr < RROWS; rr++) {
            const float ph = phi[base + (size_t)rr * NQ];
            p[rr]   = ph - rintf(ph);
            sv[rr]  = s[base + (size_t)rr * NQ];
            acc[rr] = bias2;
        }
#pragma unroll 4
        for (int k = 0; k < HIDQ; k++) {
            const float4 w  = q4[k];
            const float  ck = fmaf(ibv, w.z, w.w);   // per-column, amortized over 8 rows
            const float  v  = vv[k];
#pragma unroll
            for (int rr = 0; rr < RROWS; rr++) {
                const float z = fmaf(p[rr], w.x, fmaf(sv[rr], w.y, ck));
                acc[rr] = fmaf(tanhax(z), v, acc[rr]);
            }
        }
#pragma unroll
        for (int rr = 0; rr < RROWS; rr++)
            out[base + (size_t)rr * NQ] = acc[rr];
    }
}

extern "C" void kernel_launch(void* const* d_in, const int* in_sizes, int n_in,
                              void* d_out, int out_size)
{
    const float* phi  = (const float*)d_in[0];
    const float* s    = (const float*)d_in[1];
    const float* i_b  = (const float*)d_in[2];
    const float* w1   = (const float*)d_in[3];
    const float* b1   = (const float*)d_in[4];
    const float* w2   = (const float*)d_in[5];
    const float* b2   = (const float*)d_in[6];
    const int*   fidx = (const int*)d_in[7];
    float*       out  = (float*)d_out;

    dim3 grid(NQ / TILE, 256 / RROWS);   // (64, 32) = 2048 blocks
    soen_kernel<<<grid, TPB>>>(phi, s, i_b, w1, b1, w2, b2, fidx, out);
}

// round 3
// speedup vs baseline: 1.2319x; 1.0793x over previous
#include <cuda_runtime.h>
#include <cstdint>

#define NQ    65536
#define BQ    256
#define HIDQ  64
#define TPB   256
#define TILE  1024
#define RROWS 8
#define SCAP  516   // stash capacity; padded so row stride breaks bank alignment

__device__ __forceinline__ float tanhax(float x) {
    float y; asm("tanh.approx.f32 %0, %1;" : "=f"(y) : "f"(x)); return y;
}

__global__ __launch_bounds__(TPB) void soen_kernel(
    const float* __restrict__ phi, const float* __restrict__ s,
    const float* __restrict__ i_b, const float* __restrict__ w1,
    const float* __restrict__ b1,  const float* __restrict__ w2,
    const float* __restrict__ b2,  const int* __restrict__ fidx,
    float* __restrict__ out)
{
    __shared__ float4 q4[HIDQ];        // (w1[0][k], w1[1][k], w1[2][k], b1[k])
    __shared__ float  vv[HIDQ];        // w2[k]
    __shared__ int    cnt3;
    __shared__ int    col3[TILE];
    __shared__ float  ib3[TILE];
    __shared__ float  st_p[RROWS][SCAP];   // func3 stash: periodic(phi)
    __shared__ float  st_s[RROWS][SCAP];   // func3 stash: s

    const int t        = threadIdx.x;
    const int lane     = t & 31;
    const int tileBase = blockIdx.x * TILE;
    const int r0       = blockIdx.y * RROWS;

    if (t < HIDQ) {
        q4[t] = make_float4(w1[t], w1[HIDQ + t], w1[2 * HIDQ + t], b1[t]);
        vv[t] = w2[t];
    }
    if (t == 0) cnt3 = 0;
    __syncthreads();

    // ---- compaction: func3 columns of this tile ----
    const int4 fi4 = ((const int4*)(fidx + tileBase))[t];
    int f[4] = {fi4.x, fi4.y, fi4.z, fi4.w};
    int myrank[4];
#pragma unroll
    for (int e = 0; e < 4; e++) {
        const unsigned mask = __ballot_sync(0xffffffffu, f[e] == 3);
        int rank = -1;
        if (mask) {
            const int leader = __ffs(mask) - 1;
            int base = 0;
            if (lane == leader) base = atomicAdd(&cnt3, __popc(mask));
            base = __shfl_sync(0xffffffffu, base, leader);
            if (f[e] == 3) {
                rank = base + __popc(mask & ((1u << lane) - 1u));
                const int lc = 4 * t + e;
                col3[rank] = lc;
                ib3[rank]  = i_b[tileBase + lc];
            }
        }
        myrank[e] = rank;
    }
    __syncthreads();
    const int   c3    = cnt3;
    const float bias2 = b2[0];

    // ---- Phase A: stream; cheap funcs direct-stored; func3 (p,s) stashed to SMEM ----
#pragma unroll
    for (int rr = 0; rr < RROWS; rr++) {
        const size_t rowOff = (size_t)(r0 + rr) * NQ + tileBase;
        const float4 ph4 = ((const float4*)(phi + rowOff))[t];
        const float4 sv4 = ((const float4*)(s   + rowOff))[t];
        const float phv[4] = {ph4.x, ph4.y, ph4.z, ph4.w};
        const float svv[4] = {sv4.x, sv4.y, sv4.z, sv4.w};
#pragma unroll
        for (int e = 0; e < 4; e++) {
            const float p  = phv[e] - rintf(phv[e]);
            const float sv = svv[e];
            if (f[e] == 3) {
                const int rk = myrank[e];
                if (rk < SCAP) { st_p[rr][rk] = p; st_s[rr][rk] = sv; }
            } else {
                const float g0 = fmaxf(fabsf(p) - sv, 0.0f);
                const float g1 = tanhax(p) * (1.0f - sv);
                const float g2 = exp2f(p * p * (-14.4269504088896340736f)) - sv;
                out[rowOff + 4 * t + e] = (f[e] == 0) ? g0 : ((f[e] == 1) ? g1 : g2);
            }
        }
    }
    __syncthreads();

    // ---- Phase B: items = (func3 column) x (4-row half); 2*c3 items ----
    const int items = 2 * c3;
    for (int j = t; j < items; j += TPB) {
        int col, rbase;
        if (j < c3) { col = j;       rbase = 0; }
        else        { col = j - c3;  rbase = 4; }
        const int   lc  = col3[col];
        const float ibv = ib3[col];

        float p[4], sv[4], acc[4];
        if (col < SCAP) {
#pragma unroll
            for (int i = 0; i < 4; i++) {
                p[i]   = st_p[rbase + i][col];
                sv[i]  = st_s[rbase + i][col];
                acc[i] = bias2;
            }
        } else {  // overflow fallback (statistically never taken)
            const size_t b0 = (size_t)(r0 + rbase) * NQ + tileBase + lc;
#pragma unroll
            for (int i = 0; i < 4; i++) {
                const float ph = phi[b0 + (size_t)i * NQ];
                p[i]   = ph - rintf(ph);
                sv[i]  = s[b0 + (size_t)i * NQ];
                acc[i] = bias2;
            }
        }

#pragma unroll 8
        for (int k = 0; k < HIDQ; k++) {
            const float4 w  = q4[k];
            const float  ck = fmaf(ibv, w.z, w.w);
            const float  v  = vv[k];
#pragma unroll
            for (int i = 0; i < 4; i++) {
                const float z = fmaf(p[i], w.x, fmaf(sv[i], w.y, ck));
                acc[i] = fmaf(tanhax(z), v, acc[i]);
            }
        }

        const size_t base = (size_t)(r0 + rbase) * NQ + tileBase + lc;
#pragma unroll
        for (int i = 0; i < 4; i++)
            out[base + (size_t)i * NQ] = acc[i];
    }
}

extern "C" void kernel_launch(void* const* d_in, const int* in_sizes, int n_in,
                              void* d_out, int out_size)
{
    const float* phi  = (const float*)d_in[0];
    const float* s    = (const float*)d_in[1];
    const float* i_b  = (const float*)d_in[2];
    const float* w1   = (const float*)d_in[3];
    const float* b1   = (const float*)d_in[4];
    const float* w2   = (const float*)d_in[5];
    const float* b2   = (const float*)d_in[6];
    const int*   fidx = (const int*)d_in[7];
    float*       out  = (float*)d_out;

    dim3 grid(NQ / TILE, BQ / RROWS);   // (64, 32) = 2048 blocks
    soen_kernel<<<grid, TPB>>>(phi, s, i_b, w1, b1, w2, b2, fidx, out);
}